// round 8
// baseline (speedup 1.0000x reference)
#include <cuda_runtime.h>

// ============================================================================
// GNN 2-layer SAGEConv, algebraically fused:
//   aggX = D^-1 A x
//   p    = aggX@(Wl2 Wl1)^T + x@(Wl2 Wr1)^T + b1·Wl2^T
//   out  = D^-1 A p + aggX@(Wr2 Wl1)^T + x@(Wr2 Wr1)^T + (b1·Wr2^T + b2)
// Single fused GEMM C[M,256] = [aggX|x] @ Bcat^T + cbias; cols 0..127 -> p,
// cols 128..255 -> out (before adding agg(p)).
// ============================================================================

#define NN 50000
#define NE 800000
#define D  128

// scratch (static __device__ — no allocation allowed)
__device__ __align__(16) float g_aggX[NN * D];   // 25.6 MB
__device__ __align__(16) float g_P[NN * D];      // 25.6 MB
__device__ __align__(16) float g_Bcat[256 * 256];
__device__ __align__(16) float g_cbias[256];
__device__ float g_invdeg[NN];
__device__ int   g_deg[NN];
__device__ int   g_rowptr[NN + 1];
__device__ int   g_cursor[NN];
__device__ int   g_csr[NE];
__device__ int   g_is64;

// ---------------------------------------------------------------------------
// Edge-index dtype probe: int64 data has all-zero high 32-bit words.
// ---------------------------------------------------------------------------
__global__ void k_detect(const int* __restrict__ w, int E) {
    __shared__ int any;
    if (threadIdx.x == 0) any = 0;
    __syncthreads();
    for (int i = threadIdx.x; i < 4096 && i < E; i += blockDim.x) {
        if (w[2 * i + 1] != 0) any = 1;
    }
    __syncthreads();
    if (threadIdx.x == 0) g_is64 = (any == 0) ? 1 : 0;
}

__device__ __forceinline__ int load_idx(const void* ei, long long pos) {
    if (g_is64) return (int)((const long long*)ei)[pos];
    return ((const int*)ei)[pos];
}

// ---------------------------------------------------------------------------
// CSR build
// ---------------------------------------------------------------------------
__global__ void k_zero_deg(int n) {
    int i = blockIdx.x * blockDim.x + threadIdx.x;
    if (i < n) g_deg[i] = 0;
}

__global__ void k_count(const void* __restrict__ ei, int E) {
    int e = blockIdx.x * blockDim.x + threadIdx.x;
    if (e < E) {
        int dst = load_idx(ei, (long long)E + e);
        if ((unsigned)dst < (unsigned)NN) atomicAdd(&g_deg[dst], 1);
    }
}

// single-block exclusive scan over degrees -> rowptr, cursor, invdeg
__global__ void k_scan(int n, int E) {
    __shared__ int partial[1024];
    int t = threadIdx.x;
    const int C = (n + 1023) / 1024;
    int base = t * C;
    int sum = 0;
    for (int i = 0; i < C; i++) {
        int idx = base + i;
        if (idx < n) sum += g_deg[idx];
    }
    partial[t] = sum;
    __syncthreads();
    for (int off = 1; off < 1024; off <<= 1) {
        int v = (t >= off) ? partial[t - off] : 0;
        __syncthreads();
        partial[t] += v;
        __syncthreads();
    }
    int run = (t > 0) ? partial[t - 1] : 0;
    for (int i = 0; i < C; i++) {
        int idx = base + i;
        if (idx < n) {
            g_rowptr[idx] = run;
            g_cursor[idx] = run;
            int d = g_deg[idx];
            run += d;
            g_invdeg[idx] = 1.0f / (float)(d > 1 ? d : 1);
        }
    }
    if (t == 1023) g_rowptr[n] = partial[1023];
}

__global__ void k_fill(const void* __restrict__ ei, int E) {
    int e = blockIdx.x * blockDim.x + threadIdx.x;
    if (e < E) {
        int src = load_idx(ei, e);
        int dst = load_idx(ei, (long long)E + e);
        if ((unsigned)dst < (unsigned)NN && (unsigned)src < (unsigned)NN) {
            int pos = atomicAdd(&g_cursor[dst], 1);
            g_csr[pos] = src;
        }
    }
}

// ---------------------------------------------------------------------------
// Weight prep: Bcat[n][k] = A2[n][:] . A1[:][k]
//   A2 rows:  n<128 -> Wl2[n], else Wr2[n-128]     (each [128,256])
//   A1 cols:  k<128 -> Wl1[:,k], else Wr1[:,k-128] (each [256,128])
// ---------------------------------------------------------------------------
__global__ void k_wprep(const float* __restrict__ Wl1, const float* __restrict__ Wr1,
                        const float* __restrict__ Wl2, const float* __restrict__ Wr2) {
    __shared__ float a2[256];
    int n = blockIdx.x;
    int t = threadIdx.x;
    const float* A2row = (n < 128) ? &Wl2[n * 256] : &Wr2[(n - 128) * 256];
    a2[t] = A2row[t];
    __syncthreads();
    const float* A1 = (t < 128) ? Wl1 : Wr1;
    int k = t & 127;
    float s = 0.f;
#pragma unroll 8
    for (int j = 0; j < 256; j++) s = fmaf(a2[j], A1[j * 128 + k], s);
    g_Bcat[n * 256 + t] = s;
}

__global__ void k_bias(const float* __restrict__ Wl2, const float* __restrict__ Wr2,
                       const float* __restrict__ b1, const float* __restrict__ b2) {
    int t = threadIdx.x;
    float s = 0.f;
    if (t < 128) {
        for (int j = 0; j < 256; j++) s = fmaf(Wl2[t * 256 + j], b1[j], s);
    } else {
        int n = t - 128;
        for (int j = 0; j < 256; j++) s = fmaf(Wr2[n * 256 + j], b1[j], s);
        s += b2[n];
    }
    g_cbias[t] = s;
}

// ---------------------------------------------------------------------------
// Pull aggregation: one warp per node, float4 per lane.
// PHASE 0: feat = x,   dst = g_aggX (overwrite, scaled)
// PHASE 1: feat = g_P, dst = out (accumulate onto gemm part + bias)
// ---------------------------------------------------------------------------
template <int PHASE>
__global__ void k_agg(const float* __restrict__ xin, float* __restrict__ outp, int n) {
    int warp = (blockIdx.x * blockDim.x + threadIdx.x) >> 5;
    int lane = threadIdx.x & 31;
    if (warp >= n) return;
    const float* feat = (PHASE == 0) ? xin : g_P;
    const float4* f4 = (const float4*)feat;

    int beg = g_rowptr[warp];
    int end = g_rowptr[warp + 1];

    float ax = 0.f, ay = 0.f, az = 0.f, aw = 0.f;
    int e = beg;
    for (; e + 4 <= end; e += 4) {
        int s0 = g_csr[e + 0];
        int s1 = g_csr[e + 1];
        int s2 = g_csr[e + 2];
        int s3 = g_csr[e + 3];
        float4 v0 = f4[(size_t)s0 * 32 + lane];
        float4 v1 = f4[(size_t)s1 * 32 + lane];
        float4 v2 = f4[(size_t)s2 * 32 + lane];
        float4 v3 = f4[(size_t)s3 * 32 + lane];
        ax += v0.x + v1.x + v2.x + v3.x;
        ay += v0.y + v1.y + v2.y + v3.y;
        az += v0.z + v1.z + v2.z + v3.z;
        aw += v0.w + v1.w + v2.w + v3.w;
    }
    for (; e < end; e++) {
        int s = g_csr[e];
        float4 v = f4[(size_t)s * 32 + lane];
        ax += v.x; ay += v.y; az += v.z; aw += v.w;
    }
    float inv = g_invdeg[warp];
    if (PHASE == 0) {
        float4* d4 = (float4*)g_aggX;
        d4[(size_t)warp * 32 + lane] = make_float4(ax * inv, ay * inv, az * inv, aw * inv);
    } else {
        float4* d4 = (float4*)outp;
        float4 cur = d4[(size_t)warp * 32 + lane];
        d4[(size_t)warp * 32 + lane] =
            make_float4(cur.x + ax * inv, cur.y + ay * inv, cur.z + az * inv, cur.w + aw * inv);
    }
}

// ---------------------------------------------------------------------------
// Fused node GEMM: C[M x 256] = Acat[M x 256] @ Bcat^T + cbias
//   Acat(m,k) = k<128 ? g_aggX[m][k] : X[m][k-128]
//   cols 0..127 -> g_P,   cols 128..255 -> OUT
// Classic SGEMM: 128x128 tile, BK=8, 256 threads, 8x8 per thread.
// ---------------------------------------------------------------------------
#define BM 128
#define BN 128
#define BK 8
__global__ void __launch_bounds__(256)
k_gemm(const float* __restrict__ X, float* __restrict__ OUT, int M) {
    __shared__ float As[BK][BM];
    __shared__ float Bs[BK][BN];

    const int bn = blockIdx.x * BN;        // 0 or 128
    const int bm = blockIdx.y * BM;
    const int tid = threadIdx.x;
    const int tm = (tid / 16) * 8;
    const int tn = (tid % 16) * 8;

    const int aRow = tid >> 1;
    const int aCol4 = (tid & 1) * 4;

    float acc[8][8];
#pragma unroll
    for (int i = 0; i < 8; i++)
#pragma unroll
        for (int j = 0; j < 8; j++) acc[i][j] = 0.f;

    for (int k0 = 0; k0 < 256; k0 += BK) {
        {
            int r = bm + aRow;
            if (r > M - 1) r = M - 1;
            const float* Asrc = (k0 < 128) ? g_aggX : X;
            int kk = (k0 < 128) ? k0 : (k0 - 128);
            float4 av = *(const float4*)(&Asrc[(size_t)r * D + kk + aCol4]);
            As[aCol4 + 0][aRow] = av.x;
            As[aCol4 + 1][aRow] = av.y;
            As[aCol4 + 2][aRow] = av.z;
            As[aCol4 + 3][aRow] = av.w;
        }
        {
            int nIdx = bn + aRow;
            float4 bv = *(const float4*)(&g_Bcat[(size_t)nIdx * 256 + k0 + aCol4]);
            Bs[aCol4 + 0][aRow] = bv.x;
            Bs[aCol4 + 1][aRow] = bv.y;
            Bs[aCol4 + 2][aRow] = bv.z;
            Bs[aCol4 + 3][aRow] = bv.w;
        }
        __syncthreads();

#pragma unroll
        for (int k = 0; k < BK; k++) {
            float ra[8], rb[8];
            *(float4*)&ra[0] = *(const float4*)&As[k][tm];
            *(float4*)&ra[4] = *(const float4*)&As[k][tm + 4];
            *(float4*)&rb[0] = *(const float4*)&Bs[k][tn];
            *(float4*)&rb[4] = *(const float4*)&Bs[k][tn + 4];
#pragma unroll
            for (int i = 0; i < 8; i++)
#pragma unroll
                for (int j = 0; j < 8; j++) acc[i][j] = fmaf(ra[i], rb[j], acc[i][j]);
        }
        __syncthreads();
    }

    float bias[8];
    *(float4*)&bias[0] = *(const float4*)&g_cbias[bn + tn];
    *(float4*)&bias[4] = *(const float4*)&g_cbias[bn + tn + 4];
    float* dstBase = (bn == 0) ? g_P : OUT;
#pragma unroll
    for (int i = 0; i < 8; i++) {
        int r = bm + tm + i;
        if (r < M) {
            float4 v0 = make_float4(acc[i][0] + bias[0], acc[i][1] + bias[1],
                                    acc[i][2] + bias[2], acc[i][3] + bias[3]);
            float4 v1 = make_float4(acc[i][4] + bias[4], acc[i][5] + bias[5],
                                    acc[i][6] + bias[6], acc[i][7] + bias[7]);
            *(float4*)&dstBase[(size_t)r * D + tn] = v0;
            *(float4*)&dstBase[(size_t)r * D + tn + 4] = v1;
        }
    }
}

// ---------------------------------------------------------------------------
extern "C" void kernel_launch(void* const* d_in, const int* in_sizes, int n_in,
                              void* d_out, int out_size) {
    const float* x   = (const float*)d_in[0];
    const void*  ei  = d_in[1];                 // int32 or int64 — probed on device
    const float* Wl1 = (const float*)d_in[2];
    const float* bl1 = (const float*)d_in[3];
    const float* Wr1 = (const float*)d_in[4];
    const float* Wl2 = (const float*)d_in[5];
    const float* bl2 = (const float*)d_in[6];
    const float* Wr2 = (const float*)d_in[7];
    float* out = (float*)d_out;

    const int E = in_sizes[1] / 2;   // 800000 (element count is 2E for both dtypes)
    const int M = in_sizes[0] / D;   // 50000

    // dtype probe + CSR build
    k_detect<<<1, 256>>>((const int*)ei, E);
    k_zero_deg<<<(M + 255) / 256, 256>>>(M);
    k_count<<<(E + 255) / 256, 256>>>(ei, E);
    k_scan<<<1, 1024>>>(M, E);
    k_fill<<<(E + 255) / 256, 256>>>(ei, E);

    // fused weights + bias
    k_wprep<<<256, 256>>>(Wl1, Wr1, Wl2, Wr2);
    k_bias<<<1, 256>>>(Wl2, Wr2, bl1, bl2);

    // aggX = mean-agg(x)
    k_agg<0><<<(M + 7) / 8, 256>>>(x, nullptr, M);

    // C = [aggX|x] @ Bcat^T + cbias  -> P (cols 0..127), OUT partial (cols 128..255)
    dim3 gg(2, (M + BM - 1) / BM);
    k_gemm<<<gg, 256>>>(x, out, M);

    // OUT += mean-agg(P)
    k_agg<1><<<(M + 7) / 8, 256>>>(nullptr, out, M);
}

// round 14
// speedup vs baseline: 1.5964x; 1.5964x over previous
#include <cuda_runtime.h>
#include <cuda_bf16.h>
#include <cstdint>

// ============================================================================
// GNN 2-layer SAGEConv, algebraically fused:
//   aggX = D^-1 A x
//   p    = aggX@(Wl2 Wl1)^T + x@(Wl2 Wr1)^T + b1·Wl2^T
//   out  = D^-1 A p + aggX@(Wr2 Wl1)^T + x@(Wr2 Wr1)^T + (b1·Wr2^T + b2)
// Fused GEMM C[M,256] = Acat[M,256] @ Bcat^T + cbias with Acat = [aggX|x],
// computed on tensor cores via mma.sync bf16 with hi/lo splitting:
//   C ≈ Ah·Bh + Ah·Bl + Al·Bh     (fp32 accumulate)
// cols 0..127 -> p (g_P), cols 128..255 -> out partial; then out += agg(p).
// NOTE: tcgen05 is NOT usable — harness compiles PTX for compute_103 (no 'a').
// mma.sync/ldmatrix are baseline sm_80 PTX and compile fine.
// ============================================================================

#define NN 50000
#define NE 800000
#define D  128

// scratch (static __device__ — no allocation allowed)
__device__ __align__(16) __nv_bfloat16 g_Ah[NN * 256];   // [aggX|x] hi
__device__ __align__(16) __nv_bfloat16 g_Al[NN * 256];   // [aggX|x] lo
__device__ __align__(16) float g_P[NN * D];
__device__ __align__(16) float g_Bcat[256 * 256];
__device__ __align__(16) __nv_bfloat16 g_Bh[256 * 256];
__device__ __align__(16) __nv_bfloat16 g_Bl[256 * 256];
__device__ __align__(16) float g_cbias[256];
__device__ float g_invdeg[NN];
__device__ int   g_deg[NN];
__device__ int   g_rowptr[NN + 1];
__device__ int   g_cursor[NN];
__device__ int   g_csr[NE];
__device__ int   g_is64;
__device__ int   g_bsum[256];
__device__ int   g_boff[256];

// ---------------------------------------------------------------------------
// helpers
// ---------------------------------------------------------------------------
__device__ __forceinline__ uint32_t smem_u32(const void* p) {
    uint32_t a;
    asm("{ .reg .u64 t; cvta.to.shared.u64 t, %1; cvt.u32.u64 %0, t; }" : "=r"(a) : "l"(p));
    return a;
}

#define LDSM4(r, addr)                                                         \
    asm volatile("ldmatrix.sync.aligned.m8n8.x4.shared.b16 {%0,%1,%2,%3}, [%4];" \
                 : "=r"((r)[0]), "=r"((r)[1]), "=r"((r)[2]), "=r"((r)[3])      \
                 : "r"(addr))

#define MMA16816(c, a, b0_, b1_)                                               \
    asm volatile("mma.sync.aligned.m16n8k16.row.col.f32.bf16.bf16.f32 "        \
                 "{%0,%1,%2,%3}, {%4,%5,%6,%7}, {%8,%9}, {%0,%1,%2,%3};"       \
                 : "+f"((c)[0]), "+f"((c)[1]), "+f"((c)[2]), "+f"((c)[3])      \
                 : "r"((a)[0]), "r"((a)[1]), "r"((a)[2]), "r"((a)[3]),         \
                   "r"(b0_), "r"(b1_))

__device__ __forceinline__ uint32_t pack_bf16x2(float a, float b) {
    __nv_bfloat162 h;
    h.x = __float2bfloat16_rn(a);
    h.y = __float2bfloat16_rn(b);
    return *(uint32_t*)&h;
}
__device__ __forceinline__ void split2(float a, float b, uint32_t& hi, uint32_t& lo) {
    __nv_bfloat16 ha = __float2bfloat16_rn(a);
    __nv_bfloat16 hb = __float2bfloat16_rn(b);
    __nv_bfloat162 hh; hh.x = ha; hh.y = hb;
    hi = *(uint32_t*)&hh;
    __nv_bfloat162 ll;
    ll.x = __float2bfloat16_rn(a - __bfloat162float(ha));
    ll.y = __float2bfloat16_rn(b - __bfloat162float(hb));
    lo = *(uint32_t*)&ll;
}

// ---------------------------------------------------------------------------
// Edge-index dtype probe (int64 data has all-zero high words)
// ---------------------------------------------------------------------------
__global__ void k_detect(const int* __restrict__ w, int E) {
    __shared__ int any;
    if (threadIdx.x == 0) any = 0;
    __syncthreads();
    for (int i = threadIdx.x; i < 4096 && i < E; i += blockDim.x)
        if (w[2 * i + 1] != 0) any = 1;
    __syncthreads();
    if (threadIdx.x == 0) g_is64 = (any == 0) ? 1 : 0;
}
__device__ __forceinline__ int load_idx(const void* ei, long long pos) {
    if (g_is64) return (int)((const long long*)ei)[pos];
    return ((const int*)ei)[pos];
}

// ---------------------------------------------------------------------------
// CSR build
// ---------------------------------------------------------------------------
__global__ void k_zero_deg(int n) {
    int i = blockIdx.x * blockDim.x + threadIdx.x;
    if (i < n) g_deg[i] = 0;
}
__global__ void k_count(const void* __restrict__ ei, int E) {
    int e = blockIdx.x * blockDim.x + threadIdx.x;
    if (e < E) {
        int dst = load_idx(ei, (long long)E + e);
        if ((unsigned)dst < (unsigned)NN) atomicAdd(&g_deg[dst], 1);
    }
}
// hierarchical scan: stage 1 per-block sums
__global__ void k_scan1(int n) {
    __shared__ int s[256];
    int t = threadIdx.x, i = blockIdx.x * 256 + t;
    s[t] = (i < n) ? g_deg[i] : 0;
    __syncthreads();
    for (int o = 128; o > 0; o >>= 1) {
        if (t < o) s[t] += s[t + o];
        __syncthreads();
    }
    if (t == 0) g_bsum[blockIdx.x] = s[0];
}
// stage 2: scan block sums (nb <= 256)
__global__ void k_scan2(int nb, int n) {
    __shared__ int s[256];
    int t = threadIdx.x;
    int v = (t < nb) ? g_bsum[t] : 0;
    s[t] = v;
    __syncthreads();
    for (int o = 1; o < 256; o <<= 1) {
        int u = (t >= o) ? s[t - o] : 0;
        __syncthreads();
        s[t] += u;
        __syncthreads();
    }
    if (t < nb) g_boff[t] = s[t] - v;
    if (t == 255) g_rowptr[n] = s[255];
}
// stage 3: local scan + offset
__global__ void k_scan3(int n) {
    __shared__ int s[256];
    int t = threadIdx.x, i = blockIdx.x * 256 + t;
    int d = (i < n) ? g_deg[i] : 0;
    s[t] = d;
    __syncthreads();
    for (int o = 1; o < 256; o <<= 1) {
        int u = (t >= o) ? s[t - o] : 0;
        __syncthreads();
        s[t] += u;
        __syncthreads();
    }
    if (i < n) {
        int run = g_boff[blockIdx.x] + s[t] - d;
        g_rowptr[i] = run;
        g_cursor[i] = run;
        g_invdeg[i] = 1.0f / (float)(d > 1 ? d : 1);
    }
}
__global__ void k_fill(const void* __restrict__ ei, int E) {
    int e = blockIdx.x * blockDim.x + threadIdx.x;
    if (e < E) {
        int src = load_idx(ei, e);
        int dst = load_idx(ei, (long long)E + e);
        if ((unsigned)dst < (unsigned)NN && (unsigned)src < (unsigned)NN) {
            int pos = atomicAdd(&g_cursor[dst], 1);
            g_csr[pos] = src;
        }
    }
}

// ---------------------------------------------------------------------------
// Weight prep: Bcat[n][k] = A2[n][:] . A1[:][k]; then bf16 hi/lo split; bias.
// ---------------------------------------------------------------------------
__global__ void k_wprep(const float* __restrict__ Wl1, const float* __restrict__ Wr1,
                        const float* __restrict__ Wl2, const float* __restrict__ Wr2) {
    __shared__ float a2[256];
    int n = blockIdx.x, t = threadIdx.x;
    const float* A2row = (n < 128) ? &Wl2[n * 256] : &Wr2[(n - 128) * 256];
    a2[t] = A2row[t];
    __syncthreads();
    const float* A1 = (t < 128) ? Wl1 : Wr1;
    int k = t & 127;
    float s = 0.f;
#pragma unroll 8
    for (int j = 0; j < 256; j++) s = fmaf(a2[j], A1[j * 128 + k], s);
    g_Bcat[n * 256 + t] = s;
}
__global__ void k_bsplit() {
    int i = blockIdx.x * blockDim.x + threadIdx.x;  // 65536
    float v = g_Bcat[i];
    __nv_bfloat16 h = __float2bfloat16_rn(v);
    g_Bh[i] = h;
    g_Bl[i] = __float2bfloat16_rn(v - __bfloat162float(h));
}
__global__ void k_bias(const float* __restrict__ Wl2, const float* __restrict__ Wr2,
                       const float* __restrict__ b1, const float* __restrict__ b2) {
    int t = threadIdx.x;
    float s = 0.f;
    if (t < 128) {
        for (int j = 0; j < 256; j++) s = fmaf(Wl2[t * 256 + j], b1[j], s);
    } else {
        int n = t - 128;
        for (int j = 0; j < 256; j++) s = fmaf(Wr2[n * 256 + j], b1[j], s);
        s += b2[n];
    }
    g_cbias[t] = s;
}

// x half of Acat -> bf16 hi/lo (cols 128..255)
__global__ void k_xsplit(const float* __restrict__ x, int M) {
    int i = blockIdx.x * blockDim.x + threadIdx.x;  // over M*32
    if (i >= M * 32) return;
    int row = i >> 5;
    int c4 = (i & 31) * 4;
    float4 v = *(const float4*)&x[(size_t)row * 128 + c4];
    uint32_t h0, l0, h1, l1;
    split2(v.x, v.y, h0, l0);
    split2(v.z, v.w, h1, l1);
    size_t o = (size_t)row * 256 + 128 + c4;
    *(uint2*)&g_Ah[o] = make_uint2(h0, h1);
    *(uint2*)&g_Al[o] = make_uint2(l0, l1);
}

// ---------------------------------------------------------------------------
// Pull aggregation: one warp per node, float4 per lane.
// PHASE 0: feat = x, writes hi/lo bf16 into Acat cols 0..127
// PHASE 1: feat = g_P, accumulates into out
// ---------------------------------------------------------------------------
template <int PHASE>
__global__ void k_agg(const float* __restrict__ xin, float* __restrict__ outp, int n) {
    int warp = (blockIdx.x * blockDim.x + threadIdx.x) >> 5;
    int lane = threadIdx.x & 31;
    if (warp >= n) return;
    const float* feat = (PHASE == 0) ? xin : g_P;
    const float4* f4 = (const float4*)feat;

    int beg = g_rowptr[warp];
    int end = g_rowptr[warp + 1];
    float ax = 0.f, ay = 0.f, az = 0.f, aw = 0.f;
    int e = beg;
    for (; e + 4 <= end; e += 4) {
        int s0 = g_csr[e + 0], s1 = g_csr[e + 1], s2 = g_csr[e + 2], s3 = g_csr[e + 3];
        float4 v0 = f4[(size_t)s0 * 32 + lane];
        float4 v1 = f4[(size_t)s1 * 32 + lane];
        float4 v2 = f4[(size_t)s2 * 32 + lane];
        float4 v3 = f4[(size_t)s3 * 32 + lane];
        ax += v0.x + v1.x + v2.x + v3.x;
        ay += v0.y + v1.y + v2.y + v3.y;
        az += v0.z + v1.z + v2.z + v3.z;
        aw += v0.w + v1.w + v2.w + v3.w;
    }
    for (; e < end; e++) {
        int s = g_csr[e];
        float4 v = f4[(size_t)s * 32 + lane];
        ax += v.x; ay += v.y; az += v.z; aw += v.w;
    }
    float inv = g_invdeg[warp];
    if (PHASE == 0) {
        uint32_t h0, l0, h1, l1;
        split2(ax * inv, ay * inv, h0, l0);
        split2(az * inv, aw * inv, h1, l1);
        size_t o = (size_t)warp * 256 + lane * 4;
        *(uint2*)&g_Ah[o] = make_uint2(h0, h1);
        *(uint2*)&g_Al[o] = make_uint2(l0, l1);
    } else {
        float4* d4 = (float4*)outp;
        float4 cur = d4[(size_t)warp * 32 + lane];
        d4[(size_t)warp * 32 + lane] =
            make_float4(cur.x + ax * inv, cur.y + ay * inv, cur.z + az * inv, cur.w + aw * inv);
    }
}

// ---------------------------------------------------------------------------
// Tensor-core GEMM via mma.sync bf16 (split-3):
//   C[M,256] = Ah·Bh^T + Ah·Bl^T + Al·Bh^T + cbias
// Block 128x128, 8 warps each 64x32 (4x4 m16n8k16 tiles), K chunks of 32.
// SMEM tiles padded to 40 bf16/row (80B stride: 16B-aligned, ldmatrix
// conflict-free: banks 0,20,8,28,16,4,24,12).
// ---------------------------------------------------------------------------
__global__ void __launch_bounds__(256)
k_tgemm(float* __restrict__ OUT, int M) {
    __shared__ __align__(16) __nv_bfloat16 As[128 * 40];
    __shared__ __align__(16) __nv_bfloat16 Bs[128 * 40];

    const int tid = threadIdx.x;
    const int lane = tid & 31, wid = tid >> 5;
    const int wm = wid & 1;        // 0..1  (64-row half)
    const int wn = wid >> 1;       // 0..3  (32-col quarter)
    const int bn = blockIdx.x * 128;   // 0 or 128
    const int bm = blockIdx.y * 128;

    float acc[4][4][4];
#pragma unroll
    for (int mt = 0; mt < 4; mt++)
#pragma unroll
        for (int nt = 0; nt < 4; nt++)
#pragma unroll
            for (int q = 0; q < 4; q++) acc[mt][nt][q] = 0.f;

    // global->smem load mapping: thread -> row tid/2, 16 cols ((tid&1)*16)
    const int lrow = tid >> 1;
    const int lcol = (tid & 1) * 16;
    int grow = bm + lrow;
    if (grow > M - 1) grow = M - 1;

    const uint32_t sA = smem_u32(As);
    const uint32_t sB = smem_u32(Bs);
    // ldmatrix address components
    const int am = wm * 64 + (lane & 15);
    const int ak = (lane >> 4) << 3;
    const int bnr = wn * 32 + (lane & 7) + ((lane >> 4) << 3);
    const int bk = ((lane >> 3) & 1) << 3;

#pragma unroll 1
    for (int seg = 0; seg < 3; seg++) {
        const __nv_bfloat16* Aseg = (seg == 2) ? g_Al : g_Ah;
        const __nv_bfloat16* Bseg = (seg == 1) ? g_Bl : g_Bh;
        const __nv_bfloat16* ga = Aseg + (size_t)grow * 256 + lcol;
        const __nv_bfloat16* gb = Bseg + (size_t)(bn + lrow) * 256 + lcol;

#pragma unroll 1
        for (int kb = 0; kb < 256; kb += 32) {
            __syncthreads();
            uint4 av0 = *(const uint4*)(ga + kb);
            uint4 av1 = *(const uint4*)(ga + kb + 8);
            uint4 bv0 = *(const uint4*)(gb + kb);
            uint4 bv1 = *(const uint4*)(gb + kb + 8);
            char* pa = (char*)As + lrow * 80 + lcol * 2;
            char* pb = (char*)Bs + lrow * 80 + lcol * 2;
            *(uint4*)pa = av0;
            *(uint4*)(pa + 16) = av1;
            *(uint4*)pb = bv0;
            *(uint4*)(pb + 16) = bv1;
            __syncthreads();

#pragma unroll
            for (int ks = 0; ks < 2; ks++) {
                uint32_t af[4][4];
#pragma unroll
                for (int mt = 0; mt < 4; mt++) {
                    uint32_t addr = sA + (uint32_t)(((am + mt * 16) * 40 + ks * 16 + ak) * 2);
                    LDSM4(af[mt], addr);
                }
                uint32_t bf[2][4];
#pragma unroll
                for (int pr = 0; pr < 2; pr++) {
                    uint32_t addr = sB + (uint32_t)(((bnr + pr * 16) * 40 + ks * 16 + bk) * 2);
                    LDSM4(bf[pr], addr);
                }
#pragma unroll
                for (int mt = 0; mt < 4; mt++)
#pragma unroll
                    for (int nt = 0; nt < 4; nt++)
                        MMA16816(acc[mt][nt], af[mt], bf[nt >> 1][(nt & 1) * 2],
                                 bf[nt >> 1][(nt & 1) * 2 + 1]);
            }
        }
    }

    // epilogue: +bias, split halves to g_P / OUT
    float* dst = (bn == 0) ? g_P : OUT;
#pragma unroll
    for (int nt = 0; nt < 4; nt++) {
        int c = wn * 32 + nt * 8 + (lane & 3) * 2;       // col within half
        float b0 = g_cbias[bn + c];
        float b1 = g_cbias[bn + c + 1];
#pragma unroll
        for (int mt = 0; mt < 4; mt++) {
            int r0 = bm + wm * 64 + mt * 16 + (lane >> 2);
            if (r0 < M) {
                float2 v = make_float2(acc[mt][nt][0] + b0, acc[mt][nt][1] + b1);
                *(float2*)&dst[(size_t)r0 * 128 + c] = v;
            }
            int r1 = r0 + 8;
            if (r1 < M) {
                float2 v = make_float2(acc[mt][nt][2] + b0, acc[mt][nt][3] + b1);
                *(float2*)&dst[(size_t)r1 * 128 + c] = v;
            }
        }
    }
}

// ---------------------------------------------------------------------------
extern "C" void kernel_launch(void* const* d_in, const int* in_sizes, int n_in,
                              void* d_out, int out_size) {
    const float* x   = (const float*)d_in[0];
    const void*  ei  = d_in[1];
    const float* Wl1 = (const float*)d_in[2];
    const float* bl1 = (const float*)d_in[3];
    const float* Wr1 = (const float*)d_in[4];
    const float* Wl2 = (const float*)d_in[5];
    const float* bl2 = (const float*)d_in[6];
    const float* Wr2 = (const float*)d_in[7];
    float* out = (float*)d_out;

    const int E = in_sizes[1] / 2;
    const int M = in_sizes[0] / D;
    const int nb = (M + 255) / 256;

    // dtype probe + CSR build (hierarchical scan)
    k_detect<<<1, 256>>>((const int*)ei, E);
    k_zero_deg<<<nb, 256>>>(M);
    k_count<<<(E + 255) / 256, 256>>>(ei, E);
    k_scan1<<<nb, 256>>>(M);
    k_scan2<<<1, 256>>>(nb, M);
    k_scan3<<<nb, 256>>>(M);
    k_fill<<<(E + 255) / 256, 256>>>(ei, E);

    // fused weights + bf16 split + bias; x half of Acat
    k_wprep<<<256, 256>>>(Wl1, Wr1, Wl2, Wr2);
    k_bsplit<<<256, 256>>>();
    k_bias<<<1, 256>>>(Wl2, Wr2, bl1, bl2);
    k_xsplit<<<(M * 32 + 255) / 256, 256>>>(x, M);

    // aggX half of Acat (bf16 hi/lo) = mean-agg(x)
    k_agg<0><<<(M + 7) / 8, 256>>>(x, nullptr, M);

    // tensor-core fused GEMM -> P (cols 0..127), OUT partial (cols 128..255)
    dim3 gg(2, (M + 127) / 128);
    k_tgemm<<<gg, 256>>>(out, M);

    // OUT += mean-agg(P)
    k_agg<1><<<(M + 7) / 8, 256>>>(nullptr, out, M);
}

// round 15
// speedup vs baseline: 1.9881x; 1.2454x over previous
#include <cuda_runtime.h>
#include <cuda_fp16.h>
#include <cstdint>

// ============================================================================
// GNN 2-layer SAGEConv, algebraically fused:
//   aggX = D^-1 A x
//   p    = aggX@(Wl2 Wl1)^T + x@(Wl2 Wr1)^T + b1·Wl2^T
//   out  = D^-1 A p + aggX@(Wr2 Wl1)^T + x@(Wr2 Wr1)^T + (b1·Wr2^T + b2)
// Fused GEMM C[M,256] = Acat[M,256] @ Bcat^T + cbias with Acat = [aggX|x],
// tensor cores via mma.sync fp16 with hi/lo splitting (single fused pass):
//   C ≈ Ah·Bh + Ah·Bl + Al·Bh    (fp32 accumulate, residual ~2^-24)
// cols 0..127 -> p (g_P16, fp16), cols 128..255 -> out partial; out += agg(p).
// Aggregations gather fp16 (half the L2 traffic), accumulate fp32.
// NOTE: harness compiles PTX for compute_103 (no 'a') — tcgen05 unusable;
// mma.sync/ldmatrix/cp.async are baseline sm_80 PTX.
// ============================================================================

#define NN 50000
#define NE 800000
#define D  128

// scratch (static __device__ — no allocation allowed)
__device__ __align__(16) __half g_Ah[NN * 256];   // [aggX|x] hi (x-half = fp16 x)
__device__ __align__(16) __half g_Al[NN * 256];   // [aggX|x] lo
__device__ __align__(16) __half g_P16[NN * D];    // p in fp16
__device__ __align__(16) __half g_Bh[256 * 256];
__device__ __align__(16) __half g_Bl[256 * 256];
__device__ __align__(16) float g_cbias[256];
__device__ float g_invdeg[NN];
__device__ int   g_deg[NN];
__device__ int   g_rowptr[NN + 1];
__device__ int   g_cursor[NN];
__device__ int   g_csr[NE];
__device__ int   g_src32[NE];
__device__ int   g_dst32[NE];
__device__ int   g_is64;
__device__ int   g_bsum[256];
__device__ int   g_boff[256];

// ---------------------------------------------------------------------------
// helpers
// ---------------------------------------------------------------------------
__device__ __forceinline__ uint32_t smem_u32(const void* p) {
    uint32_t a;
    asm("{ .reg .u64 t; cvta.to.shared.u64 t, %1; cvt.u32.u64 %0, t; }" : "=r"(a) : "l"(p));
    return a;
}

#define LDSM4(r, addr)                                                           \
    asm volatile("ldmatrix.sync.aligned.m8n8.x4.shared.b16 {%0,%1,%2,%3}, [%4];" \
                 : "=r"((r)[0]), "=r"((r)[1]), "=r"((r)[2]), "=r"((r)[3])        \
                 : "r"(addr))

#define MMA16816(c, a, b0_, b1_)                                                 \
    asm volatile("mma.sync.aligned.m16n8k16.row.col.f32.f16.f16.f32 "            \
                 "{%0,%1,%2,%3}, {%4,%5,%6,%7}, {%8,%9}, {%0,%1,%2,%3};"         \
                 : "+f"((c)[0]), "+f"((c)[1]), "+f"((c)[2]), "+f"((c)[3])        \
                 : "r"((a)[0]), "r"((a)[1]), "r"((a)[2]), "r"((a)[3]),           \
                   "r"(b0_), "r"(b1_))

__device__ __forceinline__ void cpasync16(uint32_t dst, const void* src) {
    asm volatile("cp.async.cg.shared.global [%0], [%1], 16;" :: "r"(dst), "l"(src));
}
#define CP_COMMIT()  asm volatile("cp.async.commit_group;" ::: "memory")
#define CP_WAIT(n)   asm volatile("cp.async.wait_group %0;" :: "n"(n) : "memory")

// fp16 hi/lo split of a pair of floats, packed as __half2 bit-patterns
__device__ __forceinline__ void split2h(float a, float b, uint32_t& hi, uint32_t& lo) {
    __half ha = __float2half_rn(a), hb = __float2half_rn(b);
    __half2 hh = __halves2half2(ha, hb);
    hi = *reinterpret_cast<uint32_t*>(&hh);
    __half2 ll = __halves2half2(__float2half_rn(a - __half2float(ha)),
                                __float2half_rn(b - __half2float(hb)));
    lo = *reinterpret_cast<uint32_t*>(&ll);
}

// ---------------------------------------------------------------------------
// Edge-index dtype probe (int64 data has all-zero high words)
// ---------------------------------------------------------------------------
__global__ void k_detect(const int* __restrict__ w, int E) {
    __shared__ int any;
    if (threadIdx.x == 0) any = 0;
    __syncthreads();
    for (int i = threadIdx.x; i < 4096 && i < E; i += blockDim.x)
        if (w[2 * i + 1] != 0) any = 1;
    __syncthreads();
    if (threadIdx.x == 0) g_is64 = (any == 0) ? 1 : 0;
}
__device__ __forceinline__ int load_idx(const void* ei, long long pos) {
    if (g_is64) return (int)((const long long*)ei)[pos];
    return ((const int*)ei)[pos];
}

// ---------------------------------------------------------------------------
// CSR build
// ---------------------------------------------------------------------------
__global__ void k_zero_deg(int n) {
    int i = blockIdx.x * blockDim.x + threadIdx.x;
    if (i < n) g_deg[i] = 0;
}
// count + stage indices as int32 (fill re-reads half the bytes)
__global__ void k_count(const void* __restrict__ ei, int E) {
    int e = blockIdx.x * blockDim.x + threadIdx.x;
    if (e < E) {
        int src = load_idx(ei, e);
        int dst = load_idx(ei, (long long)E + e);
        g_src32[e] = src;
        g_dst32[e] = dst;
        if ((unsigned)dst < (unsigned)NN) atomicAdd(&g_deg[dst], 1);
    }
}
// hierarchical scan
__global__ void k_scan1(int n) {
    __shared__ int s[256];
    int t = threadIdx.x, i = blockIdx.x * 256 + t;
    s[t] = (i < n) ? g_deg[i] : 0;
    __syncthreads();
    for (int o = 128; o > 0; o >>= 1) {
        if (t < o) s[t] += s[t + o];
        __syncthreads();
    }
    if (t == 0) g_bsum[blockIdx.x] = s[0];
}
__global__ void k_scan2(int nb, int n) {
    __shared__ int s[256];
    int t = threadIdx.x;
    int v = (t < nb) ? g_bsum[t] : 0;
    s[t] = v;
    __syncthreads();
    for (int o = 1; o < 256; o <<= 1) {
        int u = (t >= o) ? s[t - o] : 0;
        __syncthreads();
        s[t] += u;
        __syncthreads();
    }
    if (t < nb) g_boff[t] = s[t] - v;
    if (t == 255) g_rowptr[n] = s[255];
}
__global__ void k_scan3(int n) {
    __shared__ int s[256];
    int t = threadIdx.x, i = blockIdx.x * 256 + t;
    int d = (i < n) ? g_deg[i] : 0;
    s[t] = d;
    __syncthreads();
    for (int o = 1; o < 256; o <<= 1) {
        int u = (t >= o) ? s[t - o] : 0;
        __syncthreads();
        s[t] += u;
        __syncthreads();
    }
    if (i < n) {
        int run = g_boff[blockIdx.x] + s[t] - d;
        g_rowptr[i] = run;
        g_cursor[i] = run;
        g_invdeg[i] = 1.0f / (float)(d > 1 ? d : 1);
    }
}
__global__ void k_fill(int E) {
    int e = blockIdx.x * blockDim.x + threadIdx.x;
    if (e < E) {
        int src = g_src32[e];
        int dst = g_dst32[e];
        if ((unsigned)dst < (unsigned)NN && (unsigned)src < (unsigned)NN) {
            int pos = atomicAdd(&g_cursor[dst], 1);
            g_csr[pos] = src;
        }
    }
}

// ---------------------------------------------------------------------------
// Weight prep: Bcat[n][k] = A2[n][:] . A1[:][k], split fp16 hi/lo directly.
// ---------------------------------------------------------------------------
__global__ void k_wprep(const float* __restrict__ Wl1, const float* __restrict__ Wr1,
                        const float* __restrict__ Wl2, const float* __restrict__ Wr2) {
    __shared__ float a2[256];
    int n = blockIdx.x, t = threadIdx.x;
    const float* A2row = (n < 128) ? &Wl2[n * 256] : &Wr2[(n - 128) * 256];
    a2[t] = A2row[t];
    __syncthreads();
    const float* A1 = (t < 128) ? Wl1 : Wr1;
    int k = t & 127;
    float s = 0.f;
#pragma unroll 8
    for (int j = 0; j < 256; j++) s = fmaf(a2[j], A1[j * 128 + k], s);
    __half h = __float2half_rn(s);
    g_Bh[n * 256 + t] = h;
    g_Bl[n * 256 + t] = __float2half_rn(s - __half2float(h));
}
__global__ void k_bias(const float* __restrict__ Wl2, const float* __restrict__ Wr2,
                       const float* __restrict__ b1, const float* __restrict__ b2) {
    int t = threadIdx.x;
    float s = 0.f;
    if (t < 128) {
        for (int j = 0; j < 256; j++) s = fmaf(Wl2[t * 256 + j], b1[j], s);
    } else {
        int n = t - 128;
        for (int j = 0; j < 256; j++) s = fmaf(Wr2[n * 256 + j], b1[j], s);
        s += b2[n];
    }
    g_cbias[t] = s;
}

// x half of Acat -> fp16 hi/lo (cols 128..255). The hi half doubles as the
// fp16 copy of x used by the PHASE-0 aggregation gather.
__global__ void k_xsplit(const float* __restrict__ x, int M) {
    int i = blockIdx.x * blockDim.x + threadIdx.x;  // over M*32
    if (i >= M * 32) return;
    int row = i >> 5;
    int c4 = (i & 31) * 4;
    float4 v = *(const float4*)&x[(size_t)row * 128 + c4];
    uint32_t h0, l0, h1, l1;
    split2h(v.x, v.y, h0, l0);
    split2h(v.z, v.w, h1, l1);
    size_t o = (size_t)row * 256 + 128 + c4;
    *(uint2*)&g_Ah[o] = make_uint2(h0, h1);
    *(uint2*)&g_Al[o] = make_uint2(l0, l1);
}

// ---------------------------------------------------------------------------
// Pull aggregation: one warp per node, fp16 gather (8B/lane), fp32 accumulate.
// PHASE 0: gathers x (= g_Ah cols 128..255), writes hi/lo into Acat cols 0..127
// PHASE 1: gathers g_P16, accumulates into out (fp32 RMW)
// ---------------------------------------------------------------------------
template <int PHASE>
__global__ void k_agg(float* __restrict__ outp, int n) {
    int warp = (blockIdx.x * blockDim.x + threadIdx.x) >> 5;
    int lane = threadIdx.x & 31;
    if (warp >= n) return;
    // uint2 = 4 halfs. PHASE0: row stride 64 uint2 (256 halfs), base offset +32 (128 halfs).
    // PHASE1: row stride 32 uint2 (128 halfs).
    const uint2* f = (PHASE == 0) ? (const uint2*)(g_Ah + 128) : (const uint2*)g_P16;
    const int strd = (PHASE == 0) ? 64 : 32;

    int beg = g_rowptr[warp];
    int end = g_rowptr[warp + 1];
    float ax = 0.f, ay = 0.f, az = 0.f, aw = 0.f;

#define ACCV(v)                                                              \
    do {                                                                     \
        __half2 _h0 = *reinterpret_cast<__half2*>(&(v).x);                   \
        __half2 _h1 = *reinterpret_cast<__half2*>(&(v).y);                   \
        float2 _a = __half22float2(_h0), _b = __half22float2(_h1);           \
        ax += _a.x; ay += _a.y; az += _b.x; aw += _b.y;                      \
    } while (0)

    int e = beg;
    for (; e + 4 <= end; e += 4) {
        int s0 = g_csr[e + 0], s1 = g_csr[e + 1], s2 = g_csr[e + 2], s3 = g_csr[e + 3];
        uint2 v0 = f[(size_t)s0 * strd + lane];
        uint2 v1 = f[(size_t)s1 * strd + lane];
        uint2 v2 = f[(size_t)s2 * strd + lane];
        uint2 v3 = f[(size_t)s3 * strd + lane];
        ACCV(v0); ACCV(v1); ACCV(v2); ACCV(v3);
    }
    for (; e < end; e++) {
        uint2 v = f[(size_t)g_csr[e] * strd + lane];
        ACCV(v);
    }
#undef ACCV

    float inv = g_invdeg[warp];
    if (PHASE == 0) {
        uint32_t h0, l0, h1, l1;
        split2h(ax * inv, ay * inv, h0, l0);
        split2h(az * inv, aw * inv, h1, l1);
        size_t o = (size_t)warp * 256 + lane * 4;
        *(uint2*)&g_Ah[o] = make_uint2(h0, h1);
        *(uint2*)&g_Al[o] = make_uint2(l0, l1);
    } else {
        float4* d4 = (float4*)outp;
        float4 cur = d4[(size_t)warp * 32 + lane];
        d4[(size_t)warp * 32 + lane] =
            make_float4(cur.x + ax * inv, cur.y + ay * inv, cur.z + az * inv, cur.w + aw * inv);
    }
}

// ---------------------------------------------------------------------------
// Fused tensor-core GEMM (single pass, 3 products per K-chunk):
//   C[M,256] = Ah·Bh^T + Ah·Bl^T + Al·Bh^T + cbias
// Block 128x128, 8 warps each 64x32, K chunks of 32, cp.async double buffer.
// SMEM per buffer: 4 tiles (Ah,Al,Bh,Bl) of 128x40 fp16 (80B row stride,
// 16B aligned, ldmatrix conflict-free). 2 buffers = 80 KB dynamic.
// ---------------------------------------------------------------------------
#define T_AH 0
#define T_AL 10240
#define T_BH 20480
#define T_BL 30720
#define BUFB 40960
#define TG_SMEM (2 * BUFB)

__global__ void __launch_bounds__(256)
k_tgemm(float* __restrict__ OUT, int M) {
    extern __shared__ __align__(16) char smem[];
    const uint32_t sb = smem_u32(smem);

    const int tid = threadIdx.x;
    const int lane = tid & 31, wid = tid >> 5;
    const int wm = wid & 1;          // 64-row half
    const int wn = wid >> 1;         // 32-col quarter
    const int bn = blockIdx.x * 128; // 0 or 128
    const int bm = blockIdx.y * 128;

    float acc[4][4][4];
#pragma unroll
    for (int mt = 0; mt < 4; mt++)
#pragma unroll
        for (int nt = 0; nt < 4; nt++)
#pragma unroll
            for (int q = 0; q < 4; q++) acc[mt][nt][q] = 0.f;

    // global->smem mapping: thread -> row tid/2, 16 cols ((tid&1)*16)
    const int lrow = tid >> 1;
    const int lcolh = (tid & 1) * 16;       // col in halfs
    int grow = bm + lrow;
    if (grow > M - 1) grow = M - 1;
    const __half* gaH = g_Ah + (size_t)grow * 256 + lcolh;
    const __half* gaL = g_Al + (size_t)grow * 256 + lcolh;
    const __half* gbH = g_Bh + (size_t)(bn + lrow) * 256 + lcolh;
    const __half* gbL = g_Bl + (size_t)(bn + lrow) * 256 + lcolh;
    const uint32_t drow = (uint32_t)(lrow * 80 + (tid & 1) * 32);

    // ldmatrix address components (within a 128x40-half tile)
    const int am = wm * 64 + (lane & 15);
    const int ak = (lane >> 4) << 3;
    const int bnr = wn * 32 + (lane & 7) + ((lane >> 4) << 3);
    const int bk = ((lane >> 3) & 1) << 3;

    // stage chunk kb into buffer b
    auto stage = [&](int b, int kb) {
        uint32_t bb = sb + (uint32_t)b * BUFB + drow;
        cpasync16(bb + T_AH, gaH + kb);
        cpasync16(bb + T_AH + 16, gaH + kb + 8);
        cpasync16(bb + T_AL, gaL + kb);
        cpasync16(bb + T_AL + 16, gaL + kb + 8);
        cpasync16(bb + T_BH, gbH + kb);
        cpasync16(bb + T_BH + 16, gbH + kb + 8);
        cpasync16(bb + T_BL, gbL + kb);
        cpasync16(bb + T_BL + 16, gbL + kb + 8);
        CP_COMMIT();
    };

    stage(0, 0);

#pragma unroll 1
    for (int c = 0; c < 8; c++) {
        if (c < 7) stage((c + 1) & 1, (c + 1) * 32);
        if (c < 7) { CP_WAIT(1); } else { CP_WAIT(0); }
        __syncthreads();

        const uint32_t bb = sb + (uint32_t)(c & 1) * BUFB;
#pragma unroll
        for (int ks = 0; ks < 2; ks++) {
            uint32_t afh[4][4], afl[4][4];
#pragma unroll
            for (int mt = 0; mt < 4; mt++) {
                uint32_t off = (uint32_t)(((am + mt * 16) * 40 + ks * 16 + ak) * 2);
                LDSM4(afh[mt], bb + T_AH + off);
                LDSM4(afl[mt], bb + T_AL + off);
            }
            uint32_t bfh[2][4], bfl[2][4];
#pragma unroll
            for (int pr = 0; pr < 2; pr++) {
                uint32_t off = (uint32_t)(((bnr + pr * 16) * 40 + ks * 16 + bk) * 2);
                LDSM4(bfh[pr], bb + T_BH + off);
                LDSM4(bfl[pr], bb + T_BL + off);
            }
#pragma unroll
            for (int mt = 0; mt < 4; mt++)
#pragma unroll
                for (int nt = 0; nt < 4; nt++) {
                    uint32_t b0h = bfh[nt >> 1][(nt & 1) * 2], b1h = bfh[nt >> 1][(nt & 1) * 2 + 1];
                    uint32_t b0l = bfl[nt >> 1][(nt & 1) * 2], b1l = bfl[nt >> 1][(nt & 1) * 2 + 1];
                    MMA16816(acc[mt][nt], afh[mt], b0h, b1h);
                    MMA16816(acc[mt][nt], afh[mt], b0l, b1l);
                    MMA16816(acc[mt][nt], afl[mt], b0h, b1h);
                }
        }
        __syncthreads();
    }

    // epilogue: +bias; bn==0 -> g_P16 (fp16), bn==1 -> OUT (fp32)
#pragma unroll
    for (int nt = 0; nt < 4; nt++) {
        int c = wn * 32 + nt * 8 + (lane & 3) * 2;  // col within 128-half
        float b0 = g_cbias[bn + c];
        float b1 = g_cbias[bn + c + 1];
#pragma unroll
        for (int mt = 0; mt < 4; mt++) {
            int r0 = bm + wm * 64 + mt * 16 + (lane >> 2);
            int r1 = r0 + 8;
            if (bn == 0) {
                if (r0 < M) {
                    __half2 v = __floats2half2_rn(acc[mt][nt][0] + b0, acc[mt][nt][1] + b1);
                    *(__half2*)&g_P16[(size_t)r0 * 128 + c] = v;
                }
                if (r1 < M) {
                    __half2 v = __floats2half2_rn(acc[mt][nt][2] + b0, acc[mt][nt][3] + b1);
                    *(__half2*)&g_P16[(size_t)r1 * 128 + c] = v;
                }
            } else {
                if (r0 < M) {
                    *(float2*)&OUT[(size_t)r0 * 128 + c] =
                        make_float2(acc[mt][nt][0] + b0, acc[mt][nt][1] + b1);
                }
                if (r1 < M) {
                    *(float2*)&OUT[(size_t)r1 * 128 + c] =
                        make_float2(acc[mt][nt][2] + b0, acc[mt][nt][3] + b1);
                }
            }
        }
    }
}

// ---------------------------------------------------------------------------
extern "C" void kernel_launch(void* const* d_in, const int* in_sizes, int n_in,
                              void* d_out, int out_size) {
    const float* x   = (const float*)d_in[0];
    const void*  ei  = d_in[1];
    const float* Wl1 = (const float*)d_in[2];
    const float* bl1 = (const float*)d_in[3];
    const float* Wr1 = (const float*)d_in[4];
    const float* Wl2 = (const float*)d_in[5];
    const float* bl2 = (const float*)d_in[6];
    const float* Wr2 = (const float*)d_in[7];
    float* out = (float*)d_out;

    const int E = in_sizes[1] / 2;
    const int M = in_sizes[0] / D;
    const int nb = (M + 255) / 256;

    cudaFuncSetAttribute(k_tgemm, cudaFuncAttributeMaxDynamicSharedMemorySize, TG_SMEM);

    // dtype probe + CSR build (hierarchical scan; count stages int32 indices)
    k_detect<<<1, 256>>>((const int*)ei, E);
    k_zero_deg<<<nb, 256>>>(M);
    k_count<<<(E + 255) / 256, 256>>>(ei, E);
    k_scan1<<<nb, 256>>>(M);
    k_scan2<<<1, 256>>>(nb, M);
    k_scan3<<<nb, 256>>>(M);
    k_fill<<<(E + 255) / 256, 256>>>(E);

    // fused weights (fp16 split) + bias; x half of Acat
    k_wprep<<<256, 256>>>(Wl1, Wr1, Wl2, Wr2);
    k_bias<<<1, 256>>>(Wl2, Wr2, bl1, bl2);
    k_xsplit<<<(M * 32 + 255) / 256, 256>>>(x, M);

    // aggX half of Acat (fp16 hi/lo) = mean-agg(x), gathered in fp16
    k_agg<0><<<(M + 7) / 8, 256>>>(nullptr, M);

    // fused tensor-core GEMM -> P16 (cols 0..127), OUT partial (cols 128..255)
    dim3 gg(2, (M + 127) / 128);
    k_tgemm<<<gg, 256, TG_SMEM>>>(out, M);

    // OUT += mean-agg(P16)
    k_agg<1><<<(M + 7) / 8, 256>>>(out, M);
}